// round 6
// baseline (speedup 1.0000x reference)
#include <cuda_runtime.h>
#include <math.h>

#define BATCH 64
#define NPTS  512
#define DIM   512
#define NIDS  32                     // track ids are in [-1, 32)
#define CHUNKS 16                    // dist blocks per batch
#define DBLOCKS (BATCH * CHUNKS)     // 1024
#define DTHREADS 256
#define DWARPS (DTHREADS / 32)       // 8
#define APW (NPTS / CHUNKS / DWARPS) // 4 anchors per warp

__device__ __constant__ float c_margin = 0.3f;
__device__ __constant__ float c_eps    = 1e-6f;

// scratch (no allocations allowed)
__device__ float g_partial[DBLOCKS];
__device__ int   g_cnt[DBLOCKS];
__device__ unsigned int g_ticket;    // zero-initialized; reset by last block

// ---------------------------------------------------------------------------
// Single fused kernel. R5 lesson: the epilogue inflated regs 38->44 and sank
// occupancy 58%->46%, refunding the fusion win on this latency-bound kernel.
// Fix: __launch_bounds__ cap + warp-0-only minimal epilogue.
//
// Closed-form replacement for argmax-of-mask (ids in [-1, 32)):
//   pos(i) = first[m] != i ? first[m] : second[m]     (needs count[m] >= 2)
//   neg(i) = ids[j1] != m ? j1 : j2                   (needs nvalid > count[m])
// ---------------------------------------------------------------------------
__global__ void __launch_bounds__(DTHREADS, 6)
dist_kernel(const float* __restrict__ feats,
            const int*   __restrict__ ids,
            float*       __restrict__ out,
            int out_size)
{
    const int bk    = blockIdx.x;
    const int b     = bk / CHUNKS;
    const int chunk = bk % CHUNKS;
    const int wid   = threadIdx.x >> 5;
    const int lane  = threadIdx.x & 31;
    const int t     = threadIdx.x;

    __shared__ int s_first[NIDS];
    __shared__ int s_second[NIDS];
    __shared__ int s_count[NIDS];
    __shared__ int s_j1;      // first valid index overall
    __shared__ int s_j2;      // first valid index with id != ids[j1]
    __shared__ int s_idj1;    // ids[j1]
    __shared__ int s_nvalid;
    __shared__ float s_tot;
    __shared__ int   s_cnt;
    __shared__ int   s_last;

    if (t < NIDS) {
        s_first[t]  = 0x7fffffff;
        s_second[t] = 0x7fffffff;
        s_count[t]  = 0;
    }
    if (t == 0) {
        s_j1 = 0x7fffffff;
        s_j2 = 0x7fffffff;
        s_nvalid = 0;
        s_tot = 0.0f;
        s_cnt = 0;
        s_last = 0;
    }
    __syncthreads();

    // Pass 1: first occurrence per id, per-id counts, first valid overall.
    const int i0  = t;
    const int i1  = t + DTHREADS;
    const int id0 = ids[b * NPTS + i0];
    const int id1 = ids[b * NPTS + i1];
    if (id0 >= 0) {
        atomicMin(&s_first[id0], i0);
        atomicAdd(&s_count[id0], 1);
        atomicMin(&s_j1, i0);
    }
    if (id1 >= 0) {
        atomicMin(&s_first[id1], i1);
        atomicAdd(&s_count[id1], 1);
        atomicMin(&s_j1, i1);
    }
    int nv = __syncthreads_count(id0 >= 0);
    nv    += __syncthreads_count(id1 >= 0);
    if (t == 0) {
        s_nvalid = nv;
        s_idj1 = (s_j1 < NPTS) ? ids[b * NPTS + s_j1] : -2;
    }
    __syncthreads();

    // Pass 2: second occurrence per id; first valid with id != ids[j1].
    const int idj1 = s_idj1;
    if (id0 >= 0) {
        if (i0 != s_first[id0]) atomicMin(&s_second[id0], i0);
        if (id0 != idj1)        atomicMin(&s_j2, i0);
    }
    if (id1 >= 0) {
        if (i1 != s_first[id1]) atomicMin(&s_second[id1], i1);
        if (id1 != idj1)        atomicMin(&s_j2, i1);
    }
    __syncthreads();

    const int nvalid = s_nvalid;
    const int j1 = s_j1;
    const int j2 = s_j2;

    float w_tot = 0.0f;
    int   w_cnt = 0;

    const int a_base = chunk * (NPTS / CHUNKS) + wid * APW;
    const float eps = c_eps;

    for (int a = 0; a < APW; ++a) {
        const int i = a_base + a;
        const int m = ids[b * NPTS + i];          // hot in L1/L2
        if (m < 0) continue;
        const int cm = s_count[m];
        if (cm < 2) continue;                      // no positive
        if (nvalid - cm < 1) continue;             // no negative

        const int f = s_first[m];
        const int p = (f != i) ? f : s_second[m];
        const int n = (idj1 != m) ? j1 : j2;

        const float4* __restrict__ fi =
            (const float4*)(feats + ((size_t)b * NPTS + i) * DIM);
        const float4* __restrict__ fp =
            (const float4*)(feats + ((size_t)b * NPTS + p) * DIM);
        const float4* __restrict__ fn =
            (const float4*)(feats + ((size_t)b * NPTS + n) * DIM);

        float sap = 0.0f, san = 0.0f;
        #pragma unroll
        for (int k = 0; k < DIM / 4 / 32; ++k) {
            const int idx = k * 32 + lane;
            const float4 a4 = fi[idx];
            const float4 p4 = fp[idx];
            const float4 n4 = fn[idx];
            float d;
            d = a4.x - p4.x + eps; sap = fmaf(d, d, sap);
            d = a4.y - p4.y + eps; sap = fmaf(d, d, sap);
            d = a4.z - p4.z + eps; sap = fmaf(d, d, sap);
            d = a4.w - p4.w + eps; sap = fmaf(d, d, sap);
            d = a4.x - n4.x + eps; san = fmaf(d, d, san);
            d = a4.y - n4.y + eps; san = fmaf(d, d, san);
            d = a4.z - n4.z + eps; san = fmaf(d, d, san);
            d = a4.w - n4.w + eps; san = fmaf(d, d, san);
        }
        #pragma unroll
        for (int o = 16; o > 0; o >>= 1) {
            sap += __shfl_xor_sync(0xFFFFFFFFu, sap, o);
            san += __shfl_xor_sync(0xFFFFFFFFu, san, o);
        }
        if (lane == 0) {
            const float per = sqrtf(sap) - sqrtf(san) + c_margin;
            if (per > 0.0f) w_tot += per;
            w_cnt++;
        }
    }

    if (lane == 0) {
        atomicAdd(&s_tot, w_tot);
        atomicAdd(&s_cnt, w_cnt);
    }
    __syncthreads();

    // Publish partial, grab ticket; the last block finishes the job.
    if (t == 0) {
        g_partial[bk] = s_tot;
        g_cnt[bk]     = s_cnt;
        __threadfence();
        const unsigned int old = atomicAdd(&g_ticket, 1u);
        s_last = (old == DBLOCKS - 1);
    }
    __syncthreads();

    // Minimal epilogue: warp 0 only, serial strided sums + one butterfly.
    if (s_last && wid == 0) {
        float tot = 0.0f;
        int   cnt = 0;
        for (int r = 0; r < DBLOCKS / 32; ++r) {
            tot += g_partial[r * 32 + lane];
            cnt += g_cnt[r * 32 + lane];
        }
        #pragma unroll
        for (int o = 16; o > 0; o >>= 1) {
            tot += __shfl_xor_sync(0xFFFFFFFFu, tot, o);
            cnt += __shfl_xor_sync(0xFFFFFFFFu, cnt, o);
        }
        if (lane == 0) {
            const float loss = (cnt > 0) ? (tot / (float)cnt) : 0.0f;
            if (out_size > 0) out[0] = loss;   // tracking_loss
            if (out_size > 1) out[1] = loss;   // loss_triplet
            if (out_size > 2) out[2] = 0.0f;   // loss_id
            g_ticket = 0;                      // reset for next graph replay
            __threadfence();
        }
    }
}

extern "C" void kernel_launch(void* const* d_in, const int* in_sizes, int n_in,
                              void* d_out, int out_size)
{
    const float* feats = (const float*)d_in[0];
    const int*   ids   = (const int*)d_in[1];
    float*       out   = (float*)d_out;

    dist_kernel<<<DBLOCKS, DTHREADS>>>(feats, ids, out, out_size);
}

// round 7
// speedup vs baseline: 1.0949x; 1.0949x over previous
#include <cuda_runtime.h>
#include <math.h>

#define BATCH 64
#define NPTS  512
#define DIM   512
#define NIDS  32                     // track ids are in [-1, 32)
#define CHUNKS 16                    // dist blocks per batch
#define DBLOCKS (BATCH * CHUNKS)     // 1024
#define DTHREADS 256
#define DWARPS (DTHREADS / 32)       // 8
#define APW (NPTS / CHUNKS / DWARPS) // 4 anchors per warp (2 interleaved pairs)

__device__ __constant__ float c_margin = 0.3f;
__device__ __constant__ float c_eps    = 1e-6f;

// scratch (no allocations allowed) — zero-initialized; last block resets.
__device__ float        g_tot;
__device__ int          g_cntall;
__device__ unsigned int g_ticket;

// ---------------------------------------------------------------------------
// Single fused kernel, R7: the R5/R6 evidence shows a per-warp latency
// plateau (occ 46% vs 59% both ~21-23us). Fixes target warp-level
// serialization instead:
//   - 2 anchors interleaved per warp iteration (6 batched LDG.128 per k-step,
//     pipelined reduction chains, predicated validity instead of `continue`)
//   - block partials -> 2 global atomics (no 1024-partial reduce tail)
//
// Closed-form replacement for argmax-of-mask (ids in [-1, 32)):
//   pos(i) = first[m] != i ? first[m] : second[m]     (needs count[m] >= 2)
//   neg(i) = ids[j1] != m ? j1 : j2                   (needs nvalid > count[m])
// ---------------------------------------------------------------------------
__global__ void dist_kernel(const float* __restrict__ feats,
                            const int*   __restrict__ ids,
                            float*       __restrict__ out,
                            int out_size)
{
    const int bk    = blockIdx.x;
    const int b     = bk / CHUNKS;
    const int chunk = bk % CHUNKS;
    const int wid   = threadIdx.x >> 5;
    const int lane  = threadIdx.x & 31;
    const int t     = threadIdx.x;

    __shared__ int s_first[NIDS];
    __shared__ int s_second[NIDS];
    __shared__ int s_count[NIDS];
    __shared__ int s_j1;      // first valid index overall
    __shared__ int s_j2;      // first valid index with id != ids[j1]
    __shared__ int s_idj1;    // ids[j1]
    __shared__ int s_nvalid;
    __shared__ float s_tot;
    __shared__ int   s_cnt;

    if (t < NIDS) {
        s_first[t]  = 0x7fffffff;
        s_second[t] = 0x7fffffff;
        s_count[t]  = 0;
    }
    if (t == 0) {
        s_j1 = 0x7fffffff;
        s_j2 = 0x7fffffff;
        s_nvalid = 0;
        s_tot = 0.0f;
        s_cnt = 0;
    }
    __syncthreads();

    // Pass 1: first occurrence per id, per-id counts, first valid overall.
    const int i0  = t;
    const int i1  = t + DTHREADS;
    const int id0 = ids[b * NPTS + i0];
    const int id1 = ids[b * NPTS + i1];
    if (id0 >= 0) {
        atomicMin(&s_first[id0], i0);
        atomicAdd(&s_count[id0], 1);
        atomicMin(&s_j1, i0);
    }
    if (id1 >= 0) {
        atomicMin(&s_first[id1], i1);
        atomicAdd(&s_count[id1], 1);
        atomicMin(&s_j1, i1);
    }
    int nv = __syncthreads_count(id0 >= 0);
    nv    += __syncthreads_count(id1 >= 0);
    if (t == 0) {
        s_nvalid = nv;
        s_idj1 = (s_j1 < NPTS) ? ids[b * NPTS + s_j1] : -2;
    }
    __syncthreads();

    // Pass 2: second occurrence per id; first valid with id != ids[j1].
    const int idj1 = s_idj1;
    if (id0 >= 0) {
        if (i0 != s_first[id0]) atomicMin(&s_second[id0], i0);
        if (id0 != idj1)        atomicMin(&s_j2, i0);
    }
    if (id1 >= 0) {
        if (i1 != s_first[id1]) atomicMin(&s_second[id1], i1);
        if (id1 != idj1)        atomicMin(&s_j2, i1);
    }
    __syncthreads();

    const int nvalid = s_nvalid;
    const int j1 = s_j1;
    const int j2 = s_j2;

    float w_tot = 0.0f;
    int   w_cnt = 0;

    const int a_base = chunk * (NPTS / CHUNKS) + wid * APW;
    const float eps = c_eps;
    const float* __restrict__ base = feats + (size_t)b * NPTS * DIM;

    #pragma unroll
    for (int pair = 0; pair < APW / 2; ++pair) {
        const int iA = a_base + pair * 2;
        const int iB = iA + 1;

        // Resolve (p, n, ok) for both anchors; invalid -> self-row, masked.
        const int mA = ids[b * NPTS + iA];
        const int mB = ids[b * NPTS + iB];
        const int cmA = (mA >= 0) ? s_count[mA] : 0;
        const int cmB = (mB >= 0) ? s_count[mB] : 0;
        const int okA = (mA >= 0) && (cmA >= 2) && (nvalid > cmA);
        const int okB = (mB >= 0) && (cmB >= 2) && (nvalid > cmB);

        int pA = iA, nA = iA, pB = iB, nB = iB;
        if (okA) {
            const int f = s_first[mA];
            pA = (f != iA) ? f : s_second[mA];
            nA = (idj1 != mA) ? j1 : j2;
        }
        if (okB) {
            const int f = s_first[mB];
            pB = (f != iB) ? f : s_second[mB];
            nB = (idj1 != mB) ? j1 : j2;
        }

        const float4* __restrict__ fiA = (const float4*)(base + (size_t)iA * DIM);
        const float4* __restrict__ fpA = (const float4*)(base + (size_t)pA * DIM);
        const float4* __restrict__ fnA = (const float4*)(base + (size_t)nA * DIM);
        const float4* __restrict__ fiB = (const float4*)(base + (size_t)iB * DIM);
        const float4* __restrict__ fpB = (const float4*)(base + (size_t)pB * DIM);
        const float4* __restrict__ fnB = (const float4*)(base + (size_t)nB * DIM);

        float sapA = 0.0f, sanA = 0.0f, sapB = 0.0f, sanB = 0.0f;
        #pragma unroll
        for (int k = 0; k < DIM / 4 / 32; ++k) {
            const int idx = k * 32 + lane;
            const float4 aA = fiA[idx];
            const float4 pA4 = fpA[idx];
            const float4 nA4 = fnA[idx];
            const float4 aB = fiB[idx];
            const float4 pB4 = fpB[idx];
            const float4 nB4 = fnB[idx];
            float d;
            d = aA.x - pA4.x + eps; sapA = fmaf(d, d, sapA);
            d = aA.y - pA4.y + eps; sapA = fmaf(d, d, sapA);
            d = aA.z - pA4.z + eps; sapA = fmaf(d, d, sapA);
            d = aA.w - pA4.w + eps; sapA = fmaf(d, d, sapA);
            d = aA.x - nA4.x + eps; sanA = fmaf(d, d, sanA);
            d = aA.y - nA4.y + eps; sanA = fmaf(d, d, sanA);
            d = aA.z - nA4.z + eps; sanA = fmaf(d, d, sanA);
            d = aA.w - nA4.w + eps; sanA = fmaf(d, d, sanA);
            d = aB.x - pB4.x + eps; sapB = fmaf(d, d, sapB);
            d = aB.y - pB4.y + eps; sapB = fmaf(d, d, sapB);
            d = aB.z - pB4.z + eps; sapB = fmaf(d, d, sapB);
            d = aB.w - pB4.w + eps; sapB = fmaf(d, d, sapB);
            d = aB.x - nB4.x + eps; sanB = fmaf(d, d, sanB);
            d = aB.y - nB4.y + eps; sanB = fmaf(d, d, sanB);
            d = aB.z - nB4.z + eps; sanB = fmaf(d, d, sanB);
            d = aB.w - nB4.w + eps; sanB = fmaf(d, d, sanB);
        }

        // Four independent butterfly chains — pipelined by the scheduler.
        #pragma unroll
        for (int o = 16; o > 0; o >>= 1) {
            sapA += __shfl_xor_sync(0xFFFFFFFFu, sapA, o);
            sanA += __shfl_xor_sync(0xFFFFFFFFu, sanA, o);
            sapB += __shfl_xor_sync(0xFFFFFFFFu, sapB, o);
            sanB += __shfl_xor_sync(0xFFFFFFFFu, sanB, o);
        }
        if (lane == 0) {
            if (okA) {
                const float per = sqrtf(sapA) - sqrtf(sanA) + c_margin;
                if (per > 0.0f) w_tot += per;
                w_cnt++;
            }
            if (okB) {
                const float per = sqrtf(sapB) - sqrtf(sanB) + c_margin;
                if (per > 0.0f) w_tot += per;
                w_cnt++;
            }
        }
    }

    if (lane == 0) {
        atomicAdd(&s_tot, w_tot);
        atomicAdd(&s_cnt, w_cnt);
    }
    __syncthreads();

    if (t == 0) {
        atomicAdd(&g_tot, s_tot);
        atomicAdd(&g_cntall, s_cnt);
        __threadfence();
        const unsigned int old = atomicAdd(&g_ticket, 1u);
        if (old == DBLOCKS - 1) {
            __threadfence();                 // order: see all blocks' adds
            const float T = g_tot;
            const int   C = g_cntall;
            const float loss = (C > 0) ? (T / (float)C) : 0.0f;
            if (out_size > 0) out[0] = loss; // tracking_loss
            if (out_size > 1) out[1] = loss; // loss_triplet
            if (out_size > 2) out[2] = 0.0f; // loss_id
            g_tot    = 0.0f;                 // reset for next graph replay
            g_cntall = 0;
            g_ticket = 0;
            __threadfence();
        }
    }
}

extern "C" void kernel_launch(void* const* d_in, const int* in_sizes, int n_in,
                              void* d_out, int out_size)
{
    const float* feats = (const float*)d_in[0];
    const int*   ids   = (const int*)d_in[1];
    float*       out   = (float*)d_out;

    dist_kernel<<<DBLOCKS, DTHREADS>>>(feats, ids, out, out_size);
}